// round 16
// baseline (speedup 1.0000x reference)
#include <cuda_runtime.h>
#include <math.h>
#include <stdint.h>

namespace {
constexpr int BATCH = 128, NNODE = 512, INC = 128, HID = 32, KA = 100, KB = 10, OC = 10;
constexpr int KAP = 128;
constexpr int TOT = BATCH * NNODE;
constexpr int MAXE = BATCH * 8192;
constexpr float EPSV = 1e-15f;

constexpr size_t OFF_DEG    = 0;
constexpr size_t OFF_DFLAT  = OFF_DEG + TOT;
constexpr size_t OFF_LOSSB  = OFF_DFLAT + TOT;
constexpr size_t OFF_XWP    = OFF_LOSSB + BATCH;
constexpr size_t OFF_H      = OFF_XWP   + (size_t)TOT * HID;
constexpr size_t OFF_S1     = OFF_H     + (size_t)TOT * HID;
constexpr size_t OFF_X1     = OFF_S1    + (size_t)TOT * KAP;
constexpr size_t OFF_ADJ1   = OFF_X1    + (size_t)BATCH * KA * HID;
constexpr size_t OFF_DFLAT2 = OFF_ADJ1  + (size_t)BATCH * KA * KA;
constexpr size_t SCRATCH_TOTAL = OFF_DFLAT2 + (size_t)BATCH * KA;
}  // namespace

__device__ __align__(16) float g_scratch[SCRATCH_TOTAL];
__device__ __align__(16) int g_cnt_src[TOT];
__device__ __align__(16) int g_cnt_dst[TOT];
__device__ __align__(16) int g_off_src[TOT];
__device__ __align__(16) int g_off_dst[TOT];
__device__ __align__(16) int g_list_src[MAXE];
__device__ __align__(16) int g_list_dst[MAXE];

// ---------------------------------------------------------------------------
// Fused CSR build
// ---------------------------------------------------------------------------
__global__ __launch_bounds__(512) void build_csr_kernel(
    const int* __restrict__ ei, int E, int eper,
    int* __restrict__ off_src, int* __restrict__ cnt_src,
    int* __restrict__ off_dst, int* __restrict__ cnt_dst,
    int* __restrict__ list_src, int* __restrict__ list_dst,
    float* __restrict__ deg, float* __restrict__ dflat) {
    __shared__ int sc[512], sd[512], sscan[512];
    __shared__ int csrc[512], cdst[512];
    int b = blockIdx.x, tid = threadIdx.x;
    sc[tid] = 0; sd[tid] = 0;
    __syncthreads();
    const int* se = ei + (size_t)b * eper;
    const int* de = ei + E + (size_t)b * eper;
    for (int e = tid; e < eper; e += 512) {
        atomicAdd(&sc[se[e] & 511], 1);
        atomicAdd(&sd[de[e] & 511], 1);
    }
    __syncthreads();
    int vs = sc[tid], vd = sd[tid];
    int g = (b << 9) + tid;
    int base = b * eper;
    dflat[g] = (float)vs;
    deg[g]   = (float)vd;
    cnt_src[g] = vs;
    cnt_dst[g] = vd;
    sscan[tid] = vs; __syncthreads();
    for (int o = 1; o < 512; o <<= 1) {
        int t = (tid >= o) ? sscan[tid - o] : 0;
        __syncthreads(); sscan[tid] += t; __syncthreads();
    }
    int es = base + sscan[tid] - vs;
    off_src[g] = es; csrc[tid] = es;
    __syncthreads();
    sscan[tid] = vd; __syncthreads();
    for (int o = 1; o < 512; o <<= 1) {
        int t = (tid >= o) ? sscan[tid - o] : 0;
        __syncthreads(); sscan[tid] += t; __syncthreads();
    }
    int ed = base + sscan[tid] - vd;
    off_dst[g] = ed; cdst[tid] = ed;
    __syncthreads();
    for (int e = tid; e < eper; e += 512) {
        int s = se[e] & 511, d = de[e] & 511;
        int p = atomicAdd(&csrc[s], 1);
        list_src[p] = d;
        int q = atomicAdd(&cdst[d], 1);
        list_dst[q] = s;
    }
}

// ---------------------------------------------------------------------------
__global__ __launch_bounds__(256) void xwp_kernel(const float* __restrict__ x,
                                                  const float* __restrict__ W,
                                                  const float* __restrict__ deg,
                                                  float* __restrict__ xwp) {
    __shared__ float Ws[INC * HID];
    __shared__ float xs[8][INC];
    int tid = threadIdx.y * 32 + threadIdx.x;
    for (int t = tid; t < INC * HID; t += 256) Ws[t] = W[t];
    int r0 = blockIdx.x * 8;
    for (int t = tid; t < 8 * INC; t += 256) {
        int r = t >> 7, k = t & 127;
        xs[r][k] = x[(size_t)(r0 + r) * INC + k];
    }
    __syncthreads();
    int c = threadIdx.x, r = threadIdx.y;
    float acc = 0.f;
#pragma unroll 8
    for (int k = 0; k < INC; k++) acc += xs[r][k] * Ws[k * HID + c];
    int g = r0 + r;
    float dis = rsqrtf(deg[g] + 1.0f);
    xwp[(size_t)g * HID + c] = dis * acc;
}

// ---------------------------------------------------------------------------
// Fused GCN aggregate + stage-1 pooled softmax (validated R15).
// ---------------------------------------------------------------------------
__global__ __launch_bounds__(256) void agg_softmax_kernel(
    const int* __restrict__ off_dst, const int* __restrict__ cnt_dst,
    const int* __restrict__ list_dst,
    const float* __restrict__ xwp, const float* __restrict__ deg,
    const float* __restrict__ c1b,
    const float* __restrict__ W, const float* __restrict__ bias,
    float* __restrict__ h, float* __restrict__ Sout) {
    __shared__ float Ws[HID * KAP];
    __shared__ float bs[KAP];
    int tid = threadIdx.x;
    for (int t = tid; t < HID * KAP; t += 256) {
        int c = t >> 7, k = t & 127;
        Ws[t] = (k < KA) ? W[c * KA + k] : 0.f;
    }
    if (tid < KAP) bs[tid] = (tid < KA) ? bias[tid] : 0.f;
    __syncthreads();
    int lane = tid & 31, warp = tid >> 5;
    int row0 = blockIdx.x * 64 + warp * 8;
    int b = blockIdx.x >> 3;
    const float* xb = xwp + ((size_t)b << 14);
    float c1bv = c1b[lane];
    float b0v = bs[lane], b1v = bs[32 + lane], b2v = bs[64 + lane], b3v = bs[96 + lane];
#pragma unroll 1
    for (int r = 0; r < 8; r += 4) {
        float hv[4];
#pragma unroll 1
        for (int q = 0; q < 4; q++) {
            int node = row0 + r + q;
            int off = off_dst[node], cnt = cnt_dst[node];
            float acc = 0.f;
            int i = off, end = off + cnt;
            for (; i + 3 < end; i += 4) {
                int s0 = __ldg(&list_dst[i]),     s1 = __ldg(&list_dst[i + 1]);
                int s2 = __ldg(&list_dst[i + 2]), s3 = __ldg(&list_dst[i + 3]);
                acc += xb[(s0 << 5) + lane] + xb[(s1 << 5) + lane]
                     + xb[(s2 << 5) + lane] + xb[(s3 << 5) + lane];
            }
            for (; i < end; i++) acc += xb[(__ldg(&list_dst[i]) << 5) + lane];
            float dis = rsqrtf(deg[node] + 1.0f);
            float xv = xwp[((size_t)node << 5) + lane];
            float v = fmaxf(dis * (acc + xv) + c1bv, 0.f);
            hv[q] = v;
            h[((size_t)node << 5) + lane] = v;
        }
        int row = row0 + r;
        float xv0 = hv[0], xv1 = hv[1], xv2 = hv[2], xv3 = hv[3];
        float a0 = b0v, a1 = b1v, a2 = b2v, a3 = b3v;
        float c0 = b0v, c1 = b1v, c2 = b2v, c3 = b3v;
        float d0 = b0v, d1 = b1v, d2 = b2v, d3 = b3v;
        float g0 = b0v, g1 = b1v, g2 = b2v, g3 = b3v;
#pragma unroll
        for (int c = 0; c < HID; c++) {
            float bx0 = __shfl_sync(0xffffffffu, xv0, c);
            float bx1 = __shfl_sync(0xffffffffu, xv1, c);
            float bx2 = __shfl_sync(0xffffffffu, xv2, c);
            float bx3 = __shfl_sync(0xffffffffu, xv3, c);
            const float* wr = Ws + (c << 7) + lane;
            float w0 = wr[0], w1 = wr[32], w2 = wr[64], w3 = wr[96];
            a0 += bx0 * w0; a1 += bx0 * w1; a2 += bx0 * w2; a3 += bx0 * w3;
            c0 += bx1 * w0; c1 += bx1 * w1; c2 += bx1 * w2; c3 += bx1 * w3;
            d0 += bx2 * w0; d1 += bx2 * w1; d2 += bx2 * w2; d3 += bx2 * w3;
            g0 += bx3 * w0; g1 += bx3 * w1; g2 += bx3 * w2; g3 += bx3 * w3;
        }
        bool v3 = (96 + lane < KA);
        float e0 = __expf(a0), e1 = __expf(a1), e2 = __expf(a2);
        float e3 = v3 ? __expf(a3) : 0.f;
        float f0 = __expf(c0), f1 = __expf(c1), f2 = __expf(c2);
        float f3 = v3 ? __expf(c3) : 0.f;
        float h0 = __expf(d0), h1 = __expf(d1), h2 = __expf(d2);
        float h3 = v3 ? __expf(d3) : 0.f;
        float k0 = __expf(g0), k1 = __expf(g1), k2 = __expf(g2);
        float k3 = v3 ? __expf(g3) : 0.f;
        float s0 = (e0 + e1) + (e2 + e3);
        float s1 = (f0 + f1) + (f2 + f3);
        float s2 = (h0 + h1) + (h2 + h3);
        float s3 = (k0 + k1) + (k2 + k3);
#pragma unroll
        for (int o = 16; o; o >>= 1) {
            s0 += __shfl_xor_sync(0xffffffffu, s0, o);
            s1 += __shfl_xor_sync(0xffffffffu, s1, o);
            s2 += __shfl_xor_sync(0xffffffffu, s2, o);
            s3 += __shfl_xor_sync(0xffffffffu, s3, o);
        }
        float i0 = __frcp_rn(s0), i1 = __frcp_rn(s1);
        float i2 = __frcp_rn(s2), i3 = __frcp_rn(s3);
        float* op0 = Sout + (size_t)row * KAP + lane;
        op0[0] = e0 * i0; op0[32] = e1 * i0; op0[64] = e2 * i0; op0[96] = e3 * i0;
        float* op1 = Sout + (size_t)(row + 1) * KAP + lane;
        op1[0] = f0 * i1; op1[32] = f1 * i1; op1[64] = f2 * i1; op1[96] = f3 * i1;
        float* op2 = Sout + (size_t)(row + 2) * KAP + lane;
        op2[0] = h0 * i2; op2[32] = h1 * i2; op2[64] = h2 * i2; op2[96] = h3 * i2;
        float* op3 = Sout + (size_t)(row + 3) * KAP + lane;
        op3[0] = k0 * i3; op3[32] = k1 * i3; op3[64] = k2 * i3; op3[96] = k3 * i3;
    }
}

// ---------------------------------------------------------------------------
// Fused Gram + x1 + T1-gather + level-1 loss/normalize. One block per graph,
// 320 threads, 48 KB dynamic smem. T1 is never materialized in global:
// each B tile (16 T1 rows) is gathered on the fly from L2-resident s1 by
// 10 warps (warp w -> tile rows {w, w+10}), identical edge order to the old
// t1_gather kernel (bit-identical values).
// ---------------------------------------------------------------------------
__global__ __launch_bounds__(320) void gram_fused_kernel(
    const float* __restrict__ s1p, const float* __restrict__ h,
    const int* __restrict__ off_src, const int* __restrict__ cnt_src,
    const int* __restrict__ list_src,
    const float* __restrict__ dflat,
    float* __restrict__ adj1, float* __restrict__ x1,
    float* __restrict__ dflat2, float* __restrict__ lossb) {
    extern __shared__ float dyn[];
    float* AsD = dyn;           // 2*16*128
    float* BsD = dyn + 4096;
    float* HsD = dyn + 8192;
    // post-phase aliases
    float* psum  = dyn;          // 104*13
    float* diagv = dyn + 1360;   // 104
    float* idcs  = dyn + 1472;   // 104
    float* stat  = dyn + 1584;   // 91*2
    float* denp  = dyn + 1776;   // 128
    float* redv  = dyn + 1920;   // 4

    int b = blockIdx.x;
    const float* A = s1p + ((size_t)b << 16);
    const float* H = h + ((size_t)b << 14);
    const float4* s1f4 = (const float4*)A;   // row stride 32 float4
    int tid = threadIdx.x;
    int lane = tid & 31, warp = tid >> 5;

    int sel, r, c;
    if (tid < 169) {
        sel = 0; r = tid / 13; c = tid - r * 13;
    } else if (tid < 260) {
        int u = tid - 169;
        int rr = 0, base = 0, nb = 13;
#pragma unroll
        for (int q = 0; q < 12; q++) {
            if (u >= nb) { rr = q + 1; base = nb; }
            nb += 12 - q;
        }
        sel = 1; r = rr; c = rr + (u - base);
    } else if (tid < 312) {
        int u = tid - 260;
        sel = 3; r = u >> 2; c = u & 3;
    } else {
        sel = 2; r = 0; c = 0;
    }

    const float* pBbuf0;
    const float* pBbuf1;
    if (sel == 1)      { pBbuf0 = AsD; pBbuf1 = AsD + 2048; }
    else if (sel == 3) { pBbuf0 = HsD; pBbuf1 = HsD + 2048; }
    else               { pBbuf0 = BsD; pBbuf1 = BsD + 2048; }
    int aoff = r * 8, boff = c * 8;

    bool loadAB = tid < 256;
    int lk0 = tid >> 5,         lj0 = (tid & 31) << 2;
    int lk1 = (tid + 256) >> 5, lj1 = ((tid + 256) & 31) << 2;
    bool loadH = tid >= 256;
    int ht = tid - 256;
    int hk0 = ht >> 3,        hj0 = (ht & 7) << 2;
    int hk1 = (ht + 64) >> 3, hj1 = ((ht + 64) & 7) << 2;

    // ---- B-tile gather: warp w handles tile rows {w, w+10} (<16) ----
    auto gatherB = [&](int n0, float* Bdst) {
        for (int rr = warp; rr < 16; rr += 10) {
            int node = (b << 9) + n0 + rr;
            int off = off_src[node], cnt = cnt_src[node];
            float4 acc = make_float4(0.f, 0.f, 0.f, 0.f);
            int i = off, end = off + cnt;
            for (; i + 3 < end; i += 4) {
                int d0 = __ldg(&list_src[i]),     d1 = __ldg(&list_src[i + 1]);
                int d2 = __ldg(&list_src[i + 2]), d3 = __ldg(&list_src[i + 3]);
                float4 v0 = __ldg(&s1f4[(d0 << 5) + lane]);
                float4 v1 = __ldg(&s1f4[(d1 << 5) + lane]);
                float4 v2 = __ldg(&s1f4[(d2 << 5) + lane]);
                float4 v3 = __ldg(&s1f4[(d3 << 5) + lane]);
                acc.x += (v0.x + v1.x) + (v2.x + v3.x);
                acc.y += (v0.y + v1.y) + (v2.y + v3.y);
                acc.z += (v0.z + v1.z) + (v2.z + v3.z);
                acc.w += (v0.w + v1.w) + (v2.w + v3.w);
            }
            for (; i < end; i++) {
                float4 v = __ldg(&s1f4[(__ldg(&list_src[i]) << 5) + lane]);
                acc.x += v.x; acc.y += v.y; acc.z += v.z; acc.w += v.w;
            }
            *(float4*)&Bdst[rr * 128 + (lane << 2)] = acc;
        }
    };

    float4 pa0, pa1, ph0, ph1;
    if (loadAB) {
        pa0 = *(const float4*)(A + lk0 * KAP + lj0);
        pa1 = *(const float4*)(A + lk1 * KAP + lj1);
        *(float4*)&AsD[lk0 * 128 + lj0] = pa0;
        *(float4*)&AsD[lk1 * 128 + lj1] = pa1;
    }
    if (loadH) {
        ph0 = *(const float4*)(H + hk0 * HID + hj0);
        ph1 = *(const float4*)(H + hk1 * HID + hj1);
        *(float4*)&HsD[hk0 * 128 + hj0] = ph0;
        *(float4*)&HsD[hk1 * 128 + hj1] = ph1;
    }
    gatherB(0, BsD);
    __syncthreads();

    float acc[8][8] = {};
    int cur = 0;
    for (int n0 = 0; n0 < NNODE; n0 += 16) {
        int nn = n0 + 16;
        if (nn < NNODE) {
            if (loadAB) {
                pa0 = *(const float4*)(A + (nn + lk0) * KAP + lj0);
                pa1 = *(const float4*)(A + (nn + lk1) * KAP + lj1);
            }
            if (loadH) {
                ph0 = *(const float4*)(H + (nn + hk0) * HID + hj0);
                ph1 = *(const float4*)(H + (nn + hk1) * HID + hj1);
            }
        }
        {
            const float* pA = AsD + cur * 2048;
            const float* pB = cur ? pBbuf1 : pBbuf0;
#pragma unroll
            for (int kk = 0; kk < 16; kk++) {
                float4 a0 = *(const float4*)(pA + kk * 128 + aoff);
                float4 a1 = *(const float4*)(pA + kk * 128 + aoff + 4);
                float4 b0 = *(const float4*)(pB + kk * 128 + boff);
                float4 b1 = *(const float4*)(pB + kk * 128 + boff + 4);
                float a[8] = {a0.x, a0.y, a0.z, a0.w, a1.x, a1.y, a1.z, a1.w};
                float bv[8] = {b0.x, b0.y, b0.z, b0.w, b1.x, b1.y, b1.z, b1.w};
#pragma unroll
                for (int u = 0; u < 8; u++)
#pragma unroll
                    for (int v = 0; v < 8; v++) acc[u][v] += a[u] * bv[v];
            }
        }
        if (nn < NNODE) {
            int nx = cur ^ 1;
            if (loadAB) {
                *(float4*)&AsD[nx * 2048 + lk0 * 128 + lj0] = pa0;
                *(float4*)&AsD[nx * 2048 + lk1 * 128 + lj1] = pa1;
            }
            if (loadH) {
                *(float4*)&HsD[nx * 2048 + hk0 * 128 + hj0] = ph0;
                *(float4*)&HsD[nx * 2048 + hk1 * 128 + hj1] = ph1;
            }
            gatherB(nn, BsD + nx * 2048);
            __syncthreads();
            cur = nx;
        }
    }
    __syncthreads();   // tiles dead; smem now post-phase scratch

    if (sel == 3) {
        float* C = x1 + (size_t)b * KA * HID;
#pragma unroll
        for (int u = 0; u < 8; u++) {
            int row = r * 8 + u;
            if (row < KA) {
                *(float4*)&C[(size_t)row * HID + c * 8] =
                    make_float4(acc[u][0], acc[u][1], acc[u][2], acc[u][3]);
                *(float4*)&C[(size_t)row * HID + c * 8 + 4] =
                    make_float4(acc[u][4], acc[u][5], acc[u][6], acc[u][7]);
            }
        }
    }
    if (sel == 0) {
#pragma unroll
        for (int u = 0; u < 8; u++) {
            float s = 0.f;
#pragma unroll
            for (int v = 0; v < 8; v++) s += acc[u][v];
            psum[(r * 8 + u) * 13 + c] = s;
        }
        if (r == c) {
#pragma unroll
            for (int u = 0; u < 8; u++) diagv[r * 8 + u] = acc[u][u];
        }
    }
    if (sel == 1) {
        float fro = 0.f;
#pragma unroll
        for (int u = 0; u < 8; u++)
#pragma unroll
            for (int v = 0; v < 8; v++) fro += acc[u][v] * acc[u][v];
        if (r != c) fro *= 2.f;
        float tr = 0.f;
        if (r == c) {
#pragma unroll
            for (int u = 0; u < 8; u++) tr += acc[u][u];
        }
        int idx = tid - 169;
        stat[2 * idx] = fro;
        stat[2 * idx + 1] = tr;
    }
    if (tid < 128) {
        const float* df = dflat + ((size_t)b << 9);
        float v = 0.f;
        for (int n = tid; n < NNODE; n += 128) {
            const float* srow = A + (size_t)n * KAP;
            float a2 = 0.f;
            for (int k = 0; k < KAP; k++) { float sv = srow[k]; a2 += sv * sv; }
            v += a2 * df[n];
        }
        denp[tid] = v;
    }
    __syncthreads();

    if (tid < 104) {
        float rf = 0.f;
#pragma unroll
        for (int cc = 0; cc < 13; cc++) rf += psum[tid * 13 + cc];
        float rdl = rf - diagv[tid];
        idcs[tid] = 1.0f / (sqrtf(rdl) + EPSV);
    } else if (tid == 104) {
        float num = 0.f;
        for (int i = 0; i < KA; i++) num += diagv[i];
        redv[0] = num;
    } else if (tid == 105) {
        float fro = 0.f, tr = 0.f;
        for (int i = 0; i < 91; i++) { fro += stat[2 * i]; tr += stat[2 * i + 1]; }
        redv[1] = fro;
        redv[2] = tr;
    }
    if (tid == 107) {
        float den = 0.f;
        for (int i = 0; i < 128; i++) den += denp[i];
        redv[3] = den;
    }
    __syncthreads();

    if (tid == 0) {
        float num = redv[0], fro = redv[1], tr = redv[2], den = redv[3];
        float nrm = sqrtf(fro);
        float orth2 = 2.f - 2.f * tr / (nrm * 10.0f);
        float ortho = sqrtf(fmaxf(orth2, 0.f));
        lossb[b] = -num / den + ortho;
    }
    if (sel == 0) {
        float* C = adj1 + (size_t)b * KA * KA;
#pragma unroll
        for (int u = 0; u < 8; u++) {
            int i = r * 8 + u;
            if (i >= KA) continue;
            float idci = idcs[i];
            float ps = 0.f;
#pragma unroll
            for (int v = 0; v < 8; v++) {
                int j = c * 8 + v;
                if (j >= KA) continue;
                if (j == i) {
                    C[(size_t)i * KA + j] = 0.f;
                } else {
                    float val = acc[u][v] * idci * idcs[j];
                    C[(size_t)i * KA + j] = val;
                    ps += acc[u][v] * idcs[j];
                }
            }
            psum[i * 13 + c] = ps;
        }
    }
    __syncthreads();
    if (tid < KA) {
        float s = 0.f;
#pragma unroll
        for (int cc = 0; cc < 13; cc++) s += psum[tid * 13 + cc];
        dflat2[(size_t)b * KA + tid] = s * idcs[tid];
    }
}

// ---------------------------------------------------------------------------
// Stage-2 mega kernel (validated R14/R15).
// ---------------------------------------------------------------------------
__global__ __launch_bounds__(256) void stage2_mega_kernel(
    const float* __restrict__ adj1, const float* __restrict__ x1,
    const float* __restrict__ relW, const float* __restrict__ relb,
    const float* __restrict__ rootW,
    const float* __restrict__ p2W, const float* __restrict__ p2b,
    const float* __restrict__ dflat2g, float* __restrict__ lossb,
    const float* __restrict__ c3rW, const float* __restrict__ c3rb,
    const float* __restrict__ c3oW,
    const float* __restrict__ l1W, const float* __restrict__ l1b,
    const float* __restrict__ l2W, const float* __restrict__ l2b,
    float* __restrict__ out) {
    extern __shared__ float sm[];
    float* adj1s = sm;
    float* x1s   = sm + 10000;
    float* relWs = sm + 13200;
    float* rootWs= sm + 14224;
    float* p2Ws  = sm + 15248;
    float* x2s   = sm + 15568;
    float* s2s   = sm + 18768;
    float* tt2s  = sm + 19768;
    float* adjr2s= sm + 20768;
    float* ss2s  = sm + 20868;
    float* adj2s = sm + 20968;
    float* idcs  = sm + 21068;
    float* x3s   = sm + 21084;
    int b = blockIdx.x, tid = threadIdx.x;
    const float* A = adj1 + (size_t)b * KA * KA;
    const float* X = x1 + (size_t)b * KA * HID;
    for (int i = tid; i < KA * KA; i += 256) adj1s[i] = A[i];
    for (int i = tid; i < KA * HID; i += 256) x1s[i] = X[i];
    for (int i = tid; i < HID * HID; i += 256) { relWs[i] = relW[i]; rootWs[i] = rootW[i]; }
    for (int i = tid; i < HID * KB; i += 256) p2Ws[i] = p2W[i];
    __syncthreads();
    int lane = tid & 31, warp = tid >> 5;
    float rb = relb[lane];
    int kk10 = lane < KB ? lane : 0;
    float p2bv = p2b[kk10];
    for (int i = warp; i < KA; i += 8) {
        float t2 = 0.f;
        const float* ar = adj1s + i * KA;
        for (int m = 0; m < KA; m++) t2 += ar[m] * x1s[(m << 5) + lane];
        float x1v = x1s[(i << 5) + lane];
        float a = rb;
#pragma unroll
        for (int k = 0; k < 32; k++)
            a += __shfl_sync(0xffffffffu, t2, k) * relWs[(k << 5) + lane]
               + __shfl_sync(0xffffffffu, x1v, k) * rootWs[(k << 5) + lane];
        float x2v = fmaxf(a, 0.f);
        x2s[(i << 5) + lane] = x2v;
        float zz = p2bv;
#pragma unroll
        for (int c = 0; c < 32; c++)
            zz += __shfl_sync(0xffffffffu, x2v, c) * p2Ws[c * KB + kk10];
        float e = (lane < KB) ? __expf(zz) : 0.f;
        float ssum = e;
#pragma unroll
        for (int o = 16; o; o >>= 1) ssum += __shfl_xor_sync(0xffffffffu, ssum, o);
        if (lane < KB) s2s[i * KB + lane] = e / ssum;
    }
    __syncthreads();
    for (int t = tid; t < KA * KB; t += 256) {
        int i = t / KB, k = t - i * KB;
        float a = 0.f;
        const float* ar = adj1s + i * KA;
        for (int m = 0; m < KA; m++) a += ar[m] * s2s[m * KB + k];
        tt2s[t] = a;
    }
    __syncthreads();
    for (int t = tid; t < 520; t += 256) {
        if (t < 100) {
            int i = t / 10, j = t - i * 10;
            float a = 0.f;
            for (int n = 0; n < KA; n++) a += s2s[n * KB + i] * tt2s[n * KB + j];
            adjr2s[t] = a;
        } else if (t < 200) {
            int u = t - 100;
            int i = u / 10, j = u - i * 10;
            float a = 0.f;
            for (int n = 0; n < KA; n++) a += s2s[n * KB + i] * s2s[n * KB + j];
            ss2s[u] = a;
        } else {
            int u = t - 200;
            int i = u >> 5, c = u & 31;
            float a = 0.f;
            for (int n = 0; n < KA; n++) a += s2s[n * KB + i] * x2s[(n << 5) + c];
            x3s[u] = a;
        }
    }
    __syncthreads();

    if (tid < 32) {
        const float* df = dflat2g + (size_t)b * KA;
        float v = (lane < KB) ? adjr2s[lane * KB + lane] : 0.f;
#pragma unroll
        for (int o = 16; o; o >>= 1) v += __shfl_xor_sync(0xffffffffu, v, o);
        float num = v;
        v = 0.f;
        for (int n = lane; n < KA; n += 32) {
            float acc = 0.f;
#pragma unroll
            for (int k = 0; k < KB; k++) { float sv = s2s[n * KB + k]; acc += sv * sv; }
            v += acc * df[n];
        }
#pragma unroll
        for (int o = 16; o; o >>= 1) v += __shfl_xor_sync(0xffffffffu, v, o);
        float den = v;
        v = 0.f;
        for (int t = lane; t < 100; t += 32) { float q = ss2s[t]; v += q * q; }
#pragma unroll
        for (int o = 16; o; o >>= 1) v += __shfl_xor_sync(0xffffffffu, v, o);
        float nrm = sqrtf(v);
        float invn = 1.0f / nrm;
        float dk = rsqrtf((float)KB);
        v = 0.f;
        for (int t = lane; t < 100; t += 32) {
            int i = t / 10, j = t - i * 10;
            float q = ss2s[t] * invn - ((i == j) ? dk : 0.f);
            v += q * q;
        }
#pragma unroll
        for (int o = 16; o; o >>= 1) v += __shfl_xor_sync(0xffffffffu, v, o);
        float ortho = sqrtf(v);
        if (lane < KB) {
            float rsum = 0.f;
            for (int j = 0; j < KB; j++) if (j != lane) rsum += adjr2s[lane * KB + j];
            idcs[lane] = 1.0f / (sqrtf(rsum) + EPSV);
        }
        __syncwarp();
        for (int t = lane; t < 100; t += 32) {
            int i = t / 10, j = t - i * 10;
            adj2s[t] = (i == j) ? 0.f : adjr2s[t] * idcs[i] * idcs[j];
        }
        if (lane == 0) lossb[b] += -num / den + ortho;
        __syncwarp();

        float x3c[10], t3c[10];
#pragma unroll
        for (int j = 0; j < 10; j++) x3c[j] = x3s[j * 32 + lane];
#pragma unroll
        for (int i = 0; i < 10; i++) {
            float a = 0.f;
#pragma unroll
            for (int j = 0; j < 10; j++) a += adj2s[i * 10 + j] * x3c[j];
            t3c[i] = a;
        }
        float rb3 = c3rb[lane];
        float g = 0.f;
#pragma unroll
        for (int i = 0; i < 10; i++) {
            float a = rb3;
#pragma unroll
            for (int k = 0; k < 32; k++)
                a += __shfl_sync(0xffffffffu, t3c[i], k) * c3rW[k * 32 + lane]
                   + __shfl_sync(0xffffffffu, x3c[i], k) * c3oW[k * 32 + lane];
            g += a;
        }
        g *= 0.1f;
        float a1 = l1b[lane];
#pragma unroll
        for (int k = 0; k < 32; k++) a1 += __shfl_sync(0xffffffffu, g, k) * l1W[k * 32 + lane];
        float gg = fmaxf(a1, 0.f);
        float a2 = l2b[kk10];
#pragma unroll
        for (int k = 0; k < 32; k++) a2 += __shfl_sync(0xffffffffu, gg, k) * l2W[k * OC + kk10];
        float val = (lane < OC) ? a2 : -INFINITY;
        float m = val;
#pragma unroll
        for (int o = 16; o; o >>= 1) m = fmaxf(m, __shfl_xor_sync(0xffffffffu, m, o));
        float e = (lane < OC) ? __expf(val - m) : 0.f;
        float ssum = e;
#pragma unroll
        for (int o = 16; o; o >>= 1) ssum += __shfl_xor_sync(0xffffffffu, ssum, o);
        if (lane < OC) out[b * OC + lane] = val - m - logf(ssum);
    }
}

__global__ void final_kernel(const float* __restrict__ lossb, float* __restrict__ out,
                             int out_size) {
    __shared__ float sm[128];
    int t = threadIdx.x;
    sm[t] = lossb[t];
    __syncthreads();
    for (int s = 64; s > 0; s >>= 1) {
        if (t < s) sm[t] += sm[t + s];
        __syncthreads();
    }
    if (t == 0 && out_size > BATCH * OC) out[BATCH * OC] = sm[0] / (float)BATCH;
}

// ---------------------------------------------------------------------------
extern "C" void kernel_launch(void* const* d_in, const int* in_sizes, int n_in,
                              void* d_out, int out_size) {
    const float* x    = (const float*)d_in[0];
    const int*   ei   = (const int*)  d_in[1];
    const float* c1W  = (const float*)d_in[3];
    const float* c1b  = (const float*)d_in[4];
    const float* p1W  = (const float*)d_in[5];
    const float* p1b  = (const float*)d_in[6];
    const float* c2rW = (const float*)d_in[7];
    const float* c2rb = (const float*)d_in[8];
    const float* c2oW = (const float*)d_in[9];
    const float* p2W  = (const float*)d_in[10];
    const float* p2b  = (const float*)d_in[11];
    const float* c3rW = (const float*)d_in[12];
    const float* c3rb = (const float*)d_in[13];
    const float* c3oW = (const float*)d_in[14];
    const float* l1W  = (const float*)d_in[15];
    const float* l1b  = (const float*)d_in[16];
    const float* l2W  = (const float*)d_in[17];
    const float* l2b  = (const float*)d_in[18];
    float* out = (float*)d_out;
    int E = in_sizes[1] / 2;
    int eper = E / BATCH;

    void* sp = nullptr;
    cudaGetSymbolAddress(&sp, g_scratch);
    float* S = (float*)sp;
    int *csn, *cdn, *osn, *odn, *lsrc, *ldst;
    cudaGetSymbolAddress((void**)&csn, g_cnt_src);
    cudaGetSymbolAddress((void**)&cdn, g_cnt_dst);
    cudaGetSymbolAddress((void**)&osn, g_off_src);
    cudaGetSymbolAddress((void**)&odn, g_off_dst);
    cudaGetSymbolAddress((void**)&lsrc, g_list_src);
    cudaGetSymbolAddress((void**)&ldst, g_list_dst);

    cudaFuncSetAttribute(gram_fused_kernel, cudaFuncAttributeMaxDynamicSharedMemorySize, 49152);
    cudaFuncSetAttribute(stage2_mega_kernel, cudaFuncAttributeMaxDynamicSharedMemorySize, 85632);

    build_csr_kernel<<<BATCH, 512>>>(ei, E, eper, osn, csn, odn, cdn, lsrc, ldst,
                                     S + OFF_DEG, S + OFF_DFLAT);
    xwp_kernel<<<TOT / 8, dim3(32, 8)>>>(x, c1W, S + OFF_DEG, S + OFF_XWP);
    agg_softmax_kernel<<<TOT / 64, 256>>>(odn, cdn, ldst, S + OFF_XWP, S + OFF_DEG,
                                          c1b, p1W, p1b, S + OFF_H, S + OFF_S1);
    gram_fused_kernel<<<BATCH, 320, 49152>>>(S + OFF_S1, S + OFF_H,
                                             osn, csn, lsrc,
                                             S + OFF_DFLAT, S + OFF_ADJ1, S + OFF_X1,
                                             S + OFF_DFLAT2, S + OFF_LOSSB);
    stage2_mega_kernel<<<BATCH, 256, 85632>>>(S + OFF_ADJ1, S + OFF_X1, c2rW, c2rb, c2oW,
                                              p2W, p2b, S + OFF_DFLAT2, S + OFF_LOSSB,
                                              c3rW, c3rb, c3oW, l1W, l1b, l2W, l2b, out);
    final_kernel<<<1, 128>>>(S + OFF_LOSSB, out, out_size);
}

// round 17
// speedup vs baseline: 1.2005x; 1.2005x over previous
#include <cuda_runtime.h>
#include <math.h>
#include <stdint.h>

namespace {
constexpr int BATCH = 128, NNODE = 512, INC = 128, HID = 32, KA = 100, KB = 10, OC = 10;
constexpr int KAP = 128;
constexpr int TOT = BATCH * NNODE;
constexpr int MAXE = BATCH * 8192;
constexpr float EPSV = 1e-15f;

constexpr size_t OFF_DEG    = 0;
constexpr size_t OFF_DFLAT  = OFF_DEG + TOT;
constexpr size_t OFF_LOSSB  = OFF_DFLAT + TOT;
constexpr size_t OFF_XWP    = OFF_LOSSB + BATCH;
constexpr size_t OFF_H      = OFF_XWP   + (size_t)TOT * HID;
constexpr size_t OFF_S1     = OFF_H     + (size_t)TOT * HID;
constexpr size_t OFF_T1     = OFF_S1    + (size_t)TOT * KAP;
constexpr size_t OFF_X1     = OFF_T1    + (size_t)TOT * KAP;
constexpr size_t OFF_ADJ1   = OFF_X1    + (size_t)BATCH * KA * HID;
constexpr size_t OFF_DFLAT2 = OFF_ADJ1  + (size_t)BATCH * KA * KA;
constexpr size_t SCRATCH_TOTAL = OFF_DFLAT2 + (size_t)BATCH * KA;
}  // namespace

__device__ __align__(16) float g_scratch[SCRATCH_TOTAL];
__device__ __align__(16) int g_cnt_src[TOT];
__device__ __align__(16) int g_cnt_dst[TOT];
__device__ __align__(16) int g_off_src[TOT];
__device__ __align__(16) int g_off_dst[TOT];
__device__ __align__(16) int g_list_src[MAXE];
__device__ __align__(16) int g_list_dst[MAXE];

// ---------------------------------------------------------------------------
// Fused CSR build
// ---------------------------------------------------------------------------
__global__ __launch_bounds__(512) void build_csr_kernel(
    const int* __restrict__ ei, int E, int eper,
    int* __restrict__ off_src, int* __restrict__ cnt_src,
    int* __restrict__ off_dst, int* __restrict__ cnt_dst,
    int* __restrict__ list_src, int* __restrict__ list_dst,
    float* __restrict__ deg, float* __restrict__ dflat) {
    __shared__ int sc[512], sd[512], sscan[512];
    __shared__ int csrc[512], cdst[512];
    int b = blockIdx.x, tid = threadIdx.x;
    sc[tid] = 0; sd[tid] = 0;
    __syncthreads();
    const int* se = ei + (size_t)b * eper;
    const int* de = ei + E + (size_t)b * eper;
    for (int e = tid; e < eper; e += 512) {
        atomicAdd(&sc[se[e] & 511], 1);
        atomicAdd(&sd[de[e] & 511], 1);
    }
    __syncthreads();
    int vs = sc[tid], vd = sd[tid];
    int g = (b << 9) + tid;
    int base = b * eper;
    dflat[g] = (float)vs;
    deg[g]   = (float)vd;
    cnt_src[g] = vs;
    cnt_dst[g] = vd;
    sscan[tid] = vs; __syncthreads();
    for (int o = 1; o < 512; o <<= 1) {
        int t = (tid >= o) ? sscan[tid - o] : 0;
        __syncthreads(); sscan[tid] += t; __syncthreads();
    }
    int es = base + sscan[tid] - vs;
    off_src[g] = es; csrc[tid] = es;
    __syncthreads();
    sscan[tid] = vd; __syncthreads();
    for (int o = 1; o < 512; o <<= 1) {
        int t = (tid >= o) ? sscan[tid - o] : 0;
        __syncthreads(); sscan[tid] += t; __syncthreads();
    }
    int ed = base + sscan[tid] - vd;
    off_dst[g] = ed; cdst[tid] = ed;
    __syncthreads();
    for (int e = tid; e < eper; e += 512) {
        int s = se[e] & 511, d = de[e] & 511;
        int p = atomicAdd(&csrc[s], 1);
        list_src[p] = d;
        int q = atomicAdd(&cdst[d], 1);
        list_dst[q] = s;
    }
}

// ---------------------------------------------------------------------------
__global__ __launch_bounds__(256) void xwp_kernel(const float* __restrict__ x,
                                                  const float* __restrict__ W,
                                                  const float* __restrict__ deg,
                                                  float* __restrict__ xwp) {
    __shared__ float Ws[INC * HID];
    __shared__ float xs[8][INC];
    int tid = threadIdx.y * 32 + threadIdx.x;
    for (int t = tid; t < INC * HID; t += 256) Ws[t] = W[t];
    int r0 = blockIdx.x * 8;
    for (int t = tid; t < 8 * INC; t += 256) {
        int r = t >> 7, k = t & 127;
        xs[r][k] = x[(size_t)(r0 + r) * INC + k];
    }
    __syncthreads();
    int c = threadIdx.x, r = threadIdx.y;
    float acc = 0.f;
#pragma unroll 8
    for (int k = 0; k < INC; k++) acc += xs[r][k] * Ws[k * HID + c];
    int g = r0 + r;
    float dis = rsqrtf(deg[g] + 1.0f);
    xwp[(size_t)g * HID + c] = dis * acc;
}

// ---------------------------------------------------------------------------
// Fused GCN aggregate + stage-1 pooled softmax (validated R15).
// ---------------------------------------------------------------------------
__global__ __launch_bounds__(256) void agg_softmax_kernel(
    const int* __restrict__ off_dst, const int* __restrict__ cnt_dst,
    const int* __restrict__ list_dst,
    const float* __restrict__ xwp, const float* __restrict__ deg,
    const float* __restrict__ c1b,
    const float* __restrict__ W, const float* __restrict__ bias,
    float* __restrict__ h, float* __restrict__ Sout) {
    __shared__ float Ws[HID * KAP];
    __shared__ float bs[KAP];
    int tid = threadIdx.x;
    for (int t = tid; t < HID * KAP; t += 256) {
        int c = t >> 7, k = t & 127;
        Ws[t] = (k < KA) ? W[c * KA + k] : 0.f;
    }
    if (tid < KAP) bs[tid] = (tid < KA) ? bias[tid] : 0.f;
    __syncthreads();
    int lane = tid & 31, warp = tid >> 5;
    int row0 = blockIdx.x * 64 + warp * 8;
    int b = blockIdx.x >> 3;
    const float* xb = xwp + ((size_t)b << 14);
    float c1bv = c1b[lane];
    float b0v = bs[lane], b1v = bs[32 + lane], b2v = bs[64 + lane], b3v = bs[96 + lane];
#pragma unroll 1
    for (int r = 0; r < 8; r += 4) {
        float hv[4];
#pragma unroll 1
        for (int q = 0; q < 4; q++) {
            int node = row0 + r + q;
            int off = off_dst[node], cnt = cnt_dst[node];
            float acc = 0.f;
            int i = off, end = off + cnt;
            for (; i + 3 < end; i += 4) {
                int s0 = __ldg(&list_dst[i]),     s1 = __ldg(&list_dst[i + 1]);
                int s2 = __ldg(&list_dst[i + 2]), s3 = __ldg(&list_dst[i + 3]);
                acc += xb[(s0 << 5) + lane] + xb[(s1 << 5) + lane]
                     + xb[(s2 << 5) + lane] + xb[(s3 << 5) + lane];
            }
            for (; i < end; i++) acc += xb[(__ldg(&list_dst[i]) << 5) + lane];
            float dis = rsqrtf(deg[node] + 1.0f);
            float xv = xwp[((size_t)node << 5) + lane];
            float v = fmaxf(dis * (acc + xv) + c1bv, 0.f);
            hv[q] = v;
            h[((size_t)node << 5) + lane] = v;
        }
        int row = row0 + r;
        float xv0 = hv[0], xv1 = hv[1], xv2 = hv[2], xv3 = hv[3];
        float a0 = b0v, a1 = b1v, a2 = b2v, a3 = b3v;
        float c0 = b0v, c1 = b1v, c2 = b2v, c3 = b3v;
        float d0 = b0v, d1 = b1v, d2 = b2v, d3 = b3v;
        float g0 = b0v, g1 = b1v, g2 = b2v, g3 = b3v;
#pragma unroll
        for (int c = 0; c < HID; c++) {
            float bx0 = __shfl_sync(0xffffffffu, xv0, c);
            float bx1 = __shfl_sync(0xffffffffu, xv1, c);
            float bx2 = __shfl_sync(0xffffffffu, xv2, c);
            float bx3 = __shfl_sync(0xffffffffu, xv3, c);
            const float* wr = Ws + (c << 7) + lane;
            float w0 = wr[0], w1 = wr[32], w2 = wr[64], w3 = wr[96];
            a0 += bx0 * w0; a1 += bx0 * w1; a2 += bx0 * w2; a3 += bx0 * w3;
            c0 += bx1 * w0; c1 += bx1 * w1; c2 += bx1 * w2; c3 += bx1 * w3;
            d0 += bx2 * w0; d1 += bx2 * w1; d2 += bx2 * w2; d3 += bx2 * w3;
            g0 += bx3 * w0; g1 += bx3 * w1; g2 += bx3 * w2; g3 += bx3 * w3;
        }
        bool v3 = (96 + lane < KA);
        float e0 = __expf(a0), e1 = __expf(a1), e2 = __expf(a2);
        float e3 = v3 ? __expf(a3) : 0.f;
        float f0 = __expf(c0), f1 = __expf(c1), f2 = __expf(c2);
        float f3 = v3 ? __expf(c3) : 0.f;
        float h0 = __expf(d0), h1 = __expf(d1), h2 = __expf(d2);
        float h3 = v3 ? __expf(d3) : 0.f;
        float k0 = __expf(g0), k1 = __expf(g1), k2 = __expf(g2);
        float k3 = v3 ? __expf(g3) : 0.f;
        float s0 = (e0 + e1) + (e2 + e3);
        float s1 = (f0 + f1) + (f2 + f3);
        float s2 = (h0 + h1) + (h2 + h3);
        float s3 = (k0 + k1) + (k2 + k3);
#pragma unroll
        for (int o = 16; o; o >>= 1) {
            s0 += __shfl_xor_sync(0xffffffffu, s0, o);
            s1 += __shfl_xor_sync(0xffffffffu, s1, o);
            s2 += __shfl_xor_sync(0xffffffffu, s2, o);
            s3 += __shfl_xor_sync(0xffffffffu, s3, o);
        }
        float i0 = __frcp_rn(s0), i1 = __frcp_rn(s1);
        float i2 = __frcp_rn(s2), i3 = __frcp_rn(s3);
        float* op0 = Sout + (size_t)row * KAP + lane;
        op0[0] = e0 * i0; op0[32] = e1 * i0; op0[64] = e2 * i0; op0[96] = e3 * i0;
        float* op1 = Sout + (size_t)(row + 1) * KAP + lane;
        op1[0] = f0 * i1; op1[32] = f1 * i1; op1[64] = f2 * i1; op1[96] = f3 * i1;
        float* op2 = Sout + (size_t)(row + 2) * KAP + lane;
        op2[0] = h0 * i2; op2[32] = h1 * i2; op2[64] = h2 * i2; op2[96] = h3 * i2;
        float* op3 = Sout + (size_t)(row + 3) * KAP + lane;
        op3[0] = k0 * i3; op3[32] = k1 * i3; op3[64] = k2 * i3; op3[96] = k3 * i3;
    }
}

// ---------------------------------------------------------------------------
// T1 = A @ s1 via L2 gather, 8-wide unrolled for MLP.
// ---------------------------------------------------------------------------
__global__ __launch_bounds__(256) void t1_gather_kernel(
    const int* __restrict__ off_src, const int* __restrict__ cnt_src,
    const int* __restrict__ list_src,
    const float* __restrict__ s1p, float* __restrict__ T1) {
    int node = (blockIdx.x * blockDim.x + threadIdx.x) >> 5;
    int lane = threadIdx.x & 31;
    if (node >= TOT) return;
    int b = node >> 9;
    const float4* sb = (const float4*)(s1p + (((size_t)b << 9) << 7)) + lane;
    int off = off_src[node], cnt = cnt_src[node];
    float4 acc = make_float4(0, 0, 0, 0);
    int i = off, end = off + cnt;
    for (; i + 7 < end; i += 8) {
        int d0 = __ldg(&list_src[i]),     d1 = __ldg(&list_src[i + 1]);
        int d2 = __ldg(&list_src[i + 2]), d3 = __ldg(&list_src[i + 3]);
        int d4 = __ldg(&list_src[i + 4]), d5 = __ldg(&list_src[i + 5]);
        int d6 = __ldg(&list_src[i + 6]), d7 = __ldg(&list_src[i + 7]);
        float4 v0 = __ldg(&sb[d0 << 5]);
        float4 v1 = __ldg(&sb[d1 << 5]);
        float4 v2 = __ldg(&sb[d2 << 5]);
        float4 v3 = __ldg(&sb[d3 << 5]);
        float4 v4 = __ldg(&sb[d4 << 5]);
        float4 v5 = __ldg(&sb[d5 << 5]);
        float4 v6 = __ldg(&sb[d6 << 5]);
        float4 v7 = __ldg(&sb[d7 << 5]);
        acc.x += ((v0.x + v1.x) + (v2.x + v3.x)) + ((v4.x + v5.x) + (v6.x + v7.x));
        acc.y += ((v0.y + v1.y) + (v2.y + v3.y)) + ((v4.y + v5.y) + (v6.y + v7.y));
        acc.z += ((v0.z + v1.z) + (v2.z + v3.z)) + ((v4.z + v5.z) + (v6.z + v7.z));
        acc.w += ((v0.w + v1.w) + (v2.w + v3.w)) + ((v4.w + v5.w) + (v6.w + v7.w));
    }
    for (; i + 3 < end; i += 4) {
        int d0 = __ldg(&list_src[i]),     d1 = __ldg(&list_src[i + 1]);
        int d2 = __ldg(&list_src[i + 2]), d3 = __ldg(&list_src[i + 3]);
        float4 v0 = __ldg(&sb[d0 << 5]);
        float4 v1 = __ldg(&sb[d1 << 5]);
        float4 v2 = __ldg(&sb[d2 << 5]);
        float4 v3 = __ldg(&sb[d3 << 5]);
        acc.x += (v0.x + v1.x) + (v2.x + v3.x);
        acc.y += (v0.y + v1.y) + (v2.y + v3.y);
        acc.z += (v0.z + v1.z) + (v2.z + v3.z);
        acc.w += (v0.w + v1.w) + (v2.w + v3.w);
    }
    for (; i < end; i++) {
        float4 v = __ldg(&sb[__ldg(&list_src[i]) << 5]);
        acc.x += v.x; acc.y += v.y; acc.z += v.z; acc.w += v.w;
    }
    ((float4*)(T1 + ((size_t)node << 7)))[lane] = acc;
}

// ---------------------------------------------------------------------------
// Fused Gram + x1 + level-1 loss/normalize (validated R15). One block/graph,
// 320 threads, 48 KB dynamic smem.
// ---------------------------------------------------------------------------
__global__ __launch_bounds__(320) void gram_fused_kernel(
    const float* __restrict__ s1p, const float* __restrict__ T1,
    const float* __restrict__ h, const float* __restrict__ dflat,
    float* __restrict__ adj1, float* __restrict__ x1,
    float* __restrict__ dflat2, float* __restrict__ lossb) {
    extern __shared__ float dyn[];
    float* AsD = dyn;
    float* BsD = dyn + 4096;
    float* HsD = dyn + 8192;
    float* psum  = dyn;
    float* diagv = dyn + 1360;
    float* idcs  = dyn + 1472;
    float* stat  = dyn + 1584;
    float* denp  = dyn + 1776;
    float* redv  = dyn + 1920;

    int b = blockIdx.x;
    const float* A = s1p + ((size_t)b << 16);
    const float* B = T1 + ((size_t)b << 16);
    const float* H = h + ((size_t)b << 14);
    int tid = threadIdx.x;

    int sel, r, c;
    if (tid < 169) {
        sel = 0; r = tid / 13; c = tid - r * 13;
    } else if (tid < 260) {
        int u = tid - 169;
        int rr = 0, base = 0, nb = 13;
#pragma unroll
        for (int q = 0; q < 12; q++) {
            if (u >= nb) { rr = q + 1; base = nb; }
            nb += 12 - q;
        }
        sel = 1; r = rr; c = rr + (u - base);
    } else if (tid < 312) {
        int u = tid - 260;
        sel = 3; r = u >> 2; c = u & 3;
    } else {
        sel = 2; r = 0; c = 0;
    }

    const float* pBbuf0;
    const float* pBbuf1;
    if (sel == 1)      { pBbuf0 = AsD; pBbuf1 = AsD + 2048; }
    else if (sel == 3) { pBbuf0 = HsD; pBbuf1 = HsD + 2048; }
    else               { pBbuf0 = BsD; pBbuf1 = BsD + 2048; }
    int aoff = r * 8, boff = c * 8;

    bool loadAB = tid < 256;
    int lk0 = tid >> 5,         lj0 = (tid & 31) << 2;
    int lk1 = (tid + 256) >> 5, lj1 = ((tid + 256) & 31) << 2;
    bool loadH = tid >= 256;
    int ht = tid - 256;
    int hk0 = ht >> 3,        hj0 = (ht & 7) << 2;
    int hk1 = (ht + 64) >> 3, hj1 = ((ht + 64) & 7) << 2;

    float4 pa0, pa1, pb0, pb1, ph0, ph1;
    if (loadAB) {
        pa0 = *(const float4*)(A + lk0 * KAP + lj0);
        pa1 = *(const float4*)(A + lk1 * KAP + lj1);
        pb0 = *(const float4*)(B + lk0 * KAP + lj0);
        pb1 = *(const float4*)(B + lk1 * KAP + lj1);
        *(float4*)&AsD[lk0 * 128 + lj0] = pa0;
        *(float4*)&AsD[lk1 * 128 + lj1] = pa1;
        *(float4*)&BsD[lk0 * 128 + lj0] = pb0;
        *(float4*)&BsD[lk1 * 128 + lj1] = pb1;
    }
    if (loadH) {
        ph0 = *(const float4*)(H + hk0 * HID + hj0);
        ph1 = *(const float4*)(H + hk1 * HID + hj1);
        *(float4*)&HsD[hk0 * 128 + hj0] = ph0;
        *(float4*)&HsD[hk1 * 128 + hj1] = ph1;
    }
    __syncthreads();

    float acc[8][8] = {};
    int cur = 0;
    for (int n0 = 0; n0 < NNODE; n0 += 16) {
        int nn = n0 + 16;
        if (nn < NNODE) {
            if (loadAB) {
                pa0 = *(const float4*)(A + (nn + lk0) * KAP + lj0);
                pa1 = *(const float4*)(A + (nn + lk1) * KAP + lj1);
                pb0 = *(const float4*)(B + (nn + lk0) * KAP + lj0);
                pb1 = *(const float4*)(B + (nn + lk1) * KAP + lj1);
            }
            if (loadH) {
                ph0 = *(const float4*)(H + (nn + hk0) * HID + hj0);
                ph1 = *(const float4*)(H + (nn + hk1) * HID + hj1);
            }
        }
        {
            const float* pA = AsD + cur * 2048;
            const float* pB = cur ? pBbuf1 : pBbuf0;
#pragma unroll
            for (int kk = 0; kk < 16; kk++) {
                float4 a0 = *(const float4*)(pA + kk * 128 + aoff);
                float4 a1 = *(const float4*)(pA + kk * 128 + aoff + 4);
                float4 b0 = *(const float4*)(pB + kk * 128 + boff);
                float4 b1 = *(const float4*)(pB + kk * 128 + boff + 4);
                float a[8] = {a0.x, a0.y, a0.z, a0.w, a1.x, a1.y, a1.z, a1.w};
                float bv[8] = {b0.x, b0.y, b0.z, b0.w, b1.x, b1.y, b1.z, b1.w};
#pragma unroll
                for (int u = 0; u < 8; u++)
#pragma unroll
                    for (int v = 0; v < 8; v++) acc[u][v] += a[u] * bv[v];
            }
        }
        if (nn < NNODE) {
            int nx = cur ^ 1;
            if (loadAB) {
                *(float4*)&AsD[nx * 2048 + lk0 * 128 + lj0] = pa0;
                *(float4*)&AsD[nx * 2048 + lk1 * 128 + lj1] = pa1;
                *(float4*)&BsD[nx * 2048 + lk0 * 128 + lj0] = pb0;
                *(float4*)&BsD[nx * 2048 + lk1 * 128 + lj1] = pb1;
            }
            if (loadH) {
                *(float4*)&HsD[nx * 2048 + hk0 * 128 + hj0] = ph0;
                *(float4*)&HsD[nx * 2048 + hk1 * 128 + hj1] = ph1;
            }
            __syncthreads();
            cur = nx;
        }
    }
    __syncthreads();

    if (sel == 3) {
        float* C = x1 + (size_t)b * KA * HID;
#pragma unroll
        for (int u = 0; u < 8; u++) {
            int row = r * 8 + u;
            if (row < KA) {
                *(float4*)&C[(size_t)row * HID + c * 8] =
                    make_float4(acc[u][0], acc[u][1], acc[u][2], acc[u][3]);
                *(float4*)&C[(size_t)row * HID + c * 8 + 4] =
                    make_float4(acc[u][4], acc[u][5], acc[u][6], acc[u][7]);
            }
        }
    }
    if (sel == 0) {
#pragma unroll
        for (int u = 0; u < 8; u++) {
            float s = 0.f;
#pragma unroll
            for (int v = 0; v < 8; v++) s += acc[u][v];
            psum[(r * 8 + u) * 13 + c] = s;
        }
        if (r == c) {
#pragma unroll
            for (int u = 0; u < 8; u++) diagv[r * 8 + u] = acc[u][u];
        }
    }
    if (sel == 1) {
        float fro = 0.f;
#pragma unroll
        for (int u = 0; u < 8; u++)
#pragma unroll
            for (int v = 0; v < 8; v++) fro += acc[u][v] * acc[u][v];
        if (r != c) fro *= 2.f;
        float tr = 0.f;
        if (r == c) {
#pragma unroll
            for (int u = 0; u < 8; u++) tr += acc[u][u];
        }
        int idx = tid - 169;
        stat[2 * idx] = fro;
        stat[2 * idx + 1] = tr;
    }
    if (tid < 128) {
        const float* df = dflat + ((size_t)b << 9);
        float v = 0.f;
        for (int n = tid; n < NNODE; n += 128) {
            const float* srow = A + (size_t)n * KAP;
            float a2 = 0.f;
            for (int k = 0; k < KAP; k++) { float sv = srow[k]; a2 += sv * sv; }
            v += a2 * df[n];
        }
        denp[tid] = v;
    }
    __syncthreads();

    if (tid < 104) {
        float rf = 0.f;
#pragma unroll
        for (int cc = 0; cc < 13; cc++) rf += psum[tid * 13 + cc];
        float rdl = rf - diagv[tid];
        idcs[tid] = 1.0f / (sqrtf(rdl) + EPSV);
    } else if (tid == 104) {
        float num = 0.f;
        for (int i = 0; i < KA; i++) num += diagv[i];
        redv[0] = num;
    } else if (tid == 105) {
        float fro = 0.f, tr = 0.f;
        for (int i = 0; i < 91; i++) { fro += stat[2 * i]; tr += stat[2 * i + 1]; }
        redv[1] = fro;
        redv[2] = tr;
    }
    if (tid == 107) {
        float den = 0.f;
        for (int i = 0; i < 128; i++) den += denp[i];
        redv[3] = den;
    }
    __syncthreads();

    if (tid == 0) {
        float num = redv[0], fro = redv[1], tr = redv[2], den = redv[3];
        float nrm = sqrtf(fro);
        float orth2 = 2.f - 2.f * tr / (nrm * 10.0f);
        float ortho = sqrtf(fmaxf(orth2, 0.f));
        lossb[b] = -num / den + ortho;
    }
    if (sel == 0) {
        float* C = adj1 + (size_t)b * KA * KA;
#pragma unroll
        for (int u = 0; u < 8; u++) {
            int i = r * 8 + u;
            if (i >= KA) continue;
            float idci = idcs[i];
            float ps = 0.f;
#pragma unroll
            for (int v = 0; v < 8; v++) {
                int j = c * 8 + v;
                if (j >= KA) continue;
                if (j == i) {
                    C[(size_t)i * KA + j] = 0.f;
                } else {
                    float val = acc[u][v] * idci * idcs[j];
                    C[(size_t)i * KA + j] = val;
                    ps += acc[u][v] * idcs[j];
                }
            }
            psum[i * 13 + c] = ps;
        }
    }
    __syncthreads();
    if (tid < KA) {
        float s = 0.f;
#pragma unroll
        for (int cc = 0; cc < 13; cc++) s += psum[tid * 13 + cc];
        dflat2[(size_t)b * KA + tid] = s * idcs[tid];
    }
}

// ---------------------------------------------------------------------------
// Stage-2 mega kernel (validated R14/R15).
// ---------------------------------------------------------------------------
__global__ __launch_bounds__(256) void stage2_mega_kernel(
    const float* __restrict__ adj1, const float* __restrict__ x1,
    const float* __restrict__ relW, const float* __restrict__ relb,
    const float* __restrict__ rootW,
    const float* __restrict__ p2W, const float* __restrict__ p2b,
    const float* __restrict__ dflat2g, float* __restrict__ lossb,
    const float* __restrict__ c3rW, const float* __restrict__ c3rb,
    const float* __restrict__ c3oW,
    const float* __restrict__ l1W, const float* __restrict__ l1b,
    const float* __restrict__ l2W, const float* __restrict__ l2b,
    float* __restrict__ out) {
    extern __shared__ float sm[];
    float* adj1s = sm;
    float* x1s   = sm + 10000;
    float* relWs = sm + 13200;
    float* rootWs= sm + 14224;
    float* p2Ws  = sm + 15248;
    float* x2s   = sm + 15568;
    float* s2s   = sm + 18768;
    float* tt2s  = sm + 19768;
    float* adjr2s= sm + 20768;
    float* ss2s  = sm + 20868;
    float* adj2s = sm + 20968;
    float* idcs  = sm + 21068;
    float* x3s   = sm + 21084;
    int b = blockIdx.x, tid = threadIdx.x;
    const float* A = adj1 + (size_t)b * KA * KA;
    const float* X = x1 + (size_t)b * KA * HID;
    for (int i = tid; i < KA * KA; i += 256) adj1s[i] = A[i];
    for (int i = tid; i < KA * HID; i += 256) x1s[i] = X[i];
    for (int i = tid; i < HID * HID; i += 256) { relWs[i] = relW[i]; rootWs[i] = rootW[i]; }
    for (int i = tid; i < HID * KB; i += 256) p2Ws[i] = p2W[i];
    __syncthreads();
    int lane = tid & 31, warp = tid >> 5;
    float rb = relb[lane];
    int kk10 = lane < KB ? lane : 0;
    float p2bv = p2b[kk10];
    for (int i = warp; i < KA; i += 8) {
        float t2 = 0.f;
        const float* ar = adj1s + i * KA;
        for (int m = 0; m < KA; m++) t2 += ar[m] * x1s[(m << 5) + lane];
        float x1v = x1s[(i << 5) + lane];
        float a = rb;
#pragma unroll
        for (int k = 0; k < 32; k++)
            a += __shfl_sync(0xffffffffu, t2, k) * relWs[(k << 5) + lane]
               + __shfl_sync(0xffffffffu, x1v, k) * rootWs[(k << 5) + lane];
        float x2v = fmaxf(a, 0.f);
        x2s[(i << 5) + lane] = x2v;
        float zz = p2bv;
#pragma unroll
        for (int c = 0; c < 32; c++)
            zz += __shfl_sync(0xffffffffu, x2v, c) * p2Ws[c * KB + kk10];
        float e = (lane < KB) ? __expf(zz) : 0.f;
        float ssum = e;
#pragma unroll
        for (int o = 16; o; o >>= 1) ssum += __shfl_xor_sync(0xffffffffu, ssum, o);
        if (lane < KB) s2s[i * KB + lane] = e / ssum;
    }
    __syncthreads();
    for (int t = tid; t < KA * KB; t += 256) {
        int i = t / KB, k = t - i * KB;
        float a = 0.f;
        const float* ar = adj1s + i * KA;
        for (int m = 0; m < KA; m++) a += ar[m] * s2s[m * KB + k];
        tt2s[t] = a;
    }
    __syncthreads();
    for (int t = tid; t < 520; t += 256) {
        if (t < 100) {
            int i = t / 10, j = t - i * 10;
            float a = 0.f;
            for (int n = 0; n < KA; n++) a += s2s[n * KB + i] * tt2s[n * KB + j];
            adjr2s[t] = a;
        } else if (t < 200) {
            int u = t - 100;
            int i = u / 10, j = u - i * 10;
            float a = 0.f;
            for (int n = 0; n < KA; n++) a += s2s[n * KB + i] * s2s[n * KB + j];
            ss2s[u] = a;
        } else {
            int u = t - 200;
            int i = u >> 5, c = u & 31;
            float a = 0.f;
            for (int n = 0; n < KA; n++) a += s2s[n * KB + i] * x2s[(n << 5) + c];
            x3s[u] = a;
        }
    }
    __syncthreads();

    if (tid < 32) {
        const float* df = dflat2g + (size_t)b * KA;
        float v = (lane < KB) ? adjr2s[lane * KB + lane] : 0.f;
#pragma unroll
        for (int o = 16; o; o >>= 1) v += __shfl_xor_sync(0xffffffffu, v, o);
        float num = v;
        v = 0.f;
        for (int n = lane; n < KA; n += 32) {
            float acc = 0.f;
#pragma unroll
            for (int k = 0; k < KB; k++) { float sv = s2s[n * KB + k]; acc += sv * sv; }
            v += acc * df[n];
        }
#pragma unroll
        for (int o = 16; o; o >>= 1) v += __shfl_xor_sync(0xffffffffu, v, o);
        float den = v;
        v = 0.f;
        for (int t = lane; t < 100; t += 32) { float q = ss2s[t]; v += q * q; }
#pragma unroll
        for (int o = 16; o; o >>= 1) v += __shfl_xor_sync(0xffffffffu, v, o);
        float nrm = sqrtf(v);
        float invn = 1.0f / nrm;
        float dk = rsqrtf((float)KB);
        v = 0.f;
        for (int t = lane; t < 100; t += 32) {
            int i = t / 10, j = t - i * 10;
            float q = ss2s[t] * invn - ((i == j) ? dk : 0.f);
            v += q * q;
        }
#pragma unroll
        for (int o = 16; o; o >>= 1) v += __shfl_xor_sync(0xffffffffu, v, o);
        float ortho = sqrtf(v);
        if (lane < KB) {
            float rsum = 0.f;
            for (int j = 0; j < KB; j++) if (j != lane) rsum += adjr2s[lane * KB + j];
            idcs[lane] = 1.0f / (sqrtf(rsum) + EPSV);
        }
        __syncwarp();
        for (int t = lane; t < 100; t += 32) {
            int i = t / 10, j = t - i * 10;
            adj2s[t] = (i == j) ? 0.f : adjr2s[t] * idcs[i] * idcs[j];
        }
        if (lane == 0) lossb[b] += -num / den + ortho;
        __syncwarp();

        float x3c[10], t3c[10];
#pragma unroll
        for (int j = 0; j < 10; j++) x3c[j] = x3s[j * 32 + lane];
#pragma unroll
        for (int i = 0; i < 10; i++) {
            float a = 0.f;
#pragma unroll
            for (int j = 0; j < 10; j++) a += adj2s[i * 10 + j] * x3c[j];
            t3c[i] = a;
        }
        float rb3 = c3rb[lane];
        float g = 0.f;
#pragma unroll
        for (int i = 0; i < 10; i++) {
            float a = rb3;
#pragma unroll
            for (int k = 0; k < 32; k++)
                a += __shfl_sync(0xffffffffu, t3c[i], k) * c3rW[k * 32 + lane]
                   + __shfl_sync(0xffffffffu, x3c[i], k) * c3oW[k * 32 + lane];
            g += a;
        }
        g *= 0.1f;
        float a1 = l1b[lane];
#pragma unroll
        for (int k = 0; k < 32; k++) a1 += __shfl_sync(0xffffffffu, g, k) * l1W[k * 32 + lane];
        float gg = fmaxf(a1, 0.f);
        float a2 = l2b[kk10];
#pragma unroll
        for (int k = 0; k < 32; k++) a2 += __shfl_sync(0xffffffffu, gg, k) * l2W[k * OC + kk10];
        float val = (lane < OC) ? a2 : -INFINITY;
        float m = val;
#pragma unroll
        for (int o = 16; o; o >>= 1) m = fmaxf(m, __shfl_xor_sync(0xffffffffu, m, o));
        float e = (lane < OC) ? __expf(val - m) : 0.f;
        float ssum = e;
#pragma unroll
        for (int o = 16; o; o >>= 1) ssum += __shfl_xor_sync(0xffffffffu, ssum, o);
        if (lane < OC) out[b * OC + lane] = val - m - logf(ssum);
    }
}

__global__ void final_kernel(const float* __restrict__ lossb, float* __restrict__ out,
                             int out_size) {
    __shared__ float sm[128];
    int t = threadIdx.x;
    sm[t] = lossb[t];
    __syncthreads();
    for (int s = 64; s > 0; s >>= 1) {
        if (t < s) sm[t] += sm[t + s];
        __syncthreads();
    }
    if (t == 0 && out_size > BATCH * OC) out[BATCH * OC] = sm[0] / (float)BATCH;
}

// ---------------------------------------------------------------------------
extern "C" void kernel_launch(void* const* d_in, const int* in_sizes, int n_in,
                              void* d_out, int out_size) {
    const float* x    = (const float*)d_in[0];
    const int*   ei   = (const int*)  d_in[1];
    const float* c1W  = (const float*)d_in[3];
    const float* c1b  = (const float*)d_in[4];
    const float* p1W  = (const float*)d_in[5];
    const float* p1b  = (const float*)d_in[6];
    const float* c2rW = (const float*)d_in[7];
    const float* c2rb = (const float*)d_in[8];
    const float* c2oW = (const float*)d_in[9];
    const float* p2W  = (const float*)d_in[10];
    const float* p2b  = (const float*)d_in[11];
    const float* c3rW = (const float*)d_in[12];
    const float* c3rb = (const float*)d_in[13];
    const float* c3oW = (const float*)d_in[14];
    const float* l1W  = (const float*)d_in[15];
    const float* l1b  = (const float*)d_in[16];
    const float* l2W  = (const float*)d_in[17];
    const float* l2b  = (const float*)d_in[18];
    float* out = (float*)d_out;
    int E = in_sizes[1] / 2;
    int eper = E / BATCH;

    void* sp = nullptr;
    cudaGetSymbolAddress(&sp, g_scratch);
    float* S = (float*)sp;
    int *csn, *cdn, *osn, *odn, *lsrc, *ldst;
    cudaGetSymbolAddress((void**)&csn, g_cnt_src);
    cudaGetSymbolAddress((void**)&cdn, g_cnt_dst);
    cudaGetSymbolAddress((void**)&osn, g_off_src);
    cudaGetSymbolAddress((void**)&odn, g_off_dst);
    cudaGetSymbolAddress((void**)&lsrc, g_list_src);
    cudaGetSymbolAddress((void**)&ldst, g_list_dst);

    cudaFuncSetAttribute(gram_fused_kernel, cudaFuncAttributeMaxDynamicSharedMemorySize, 49152);
    cudaFuncSetAttribute(stage2_mega_kernel, cudaFuncAttributeMaxDynamicSharedMemorySize, 85632);

    build_csr_kernel<<<BATCH, 512>>>(ei, E, eper, osn, csn, odn, cdn, lsrc, ldst,
                                     S + OFF_DEG, S + OFF_DFLAT);
    xwp_kernel<<<TOT / 8, dim3(32, 8)>>>(x, c1W, S + OFF_DEG, S + OFF_XWP);
    agg_softmax_kernel<<<TOT / 64, 256>>>(odn, cdn, ldst, S + OFF_XWP, S + OFF_DEG,
                                          c1b, p1W, p1b, S + OFF_H, S + OFF_S1);
    t1_gather_kernel<<<TOT * 32 / 256, 256>>>(osn, csn, lsrc, S + OFF_S1, S + OFF_T1);
    gram_fused_kernel<<<BATCH, 320, 49152>>>(S + OFF_S1, S + OFF_T1, S + OFF_H,
                                             S + OFF_DFLAT, S + OFF_ADJ1, S + OFF_X1,
                                             S + OFF_DFLAT2, S + OFF_LOSSB);
    stage2_mega_kernel<<<BATCH, 256, 85632>>>(S + OFF_ADJ1, S + OFF_X1, c2rW, c2rb, c2oW,
                                              p2W, p2b, S + OFF_DFLAT2, S + OFF_LOSSB,
                                              c3rW, c3rb, c3oW, l1W, l1b, l2W, l2b, out);
    final_kernel<<<1, 128>>>(S + OFF_LOSSB, out, out_size);
}